// round 13
// baseline (speedup 1.0000x reference)
#include <cuda_runtime.h>
#include <cstdint>
#include <cstddef>

#define MODEL_DIM 768
#define N_HEAD    12
#define HEAD_DIM  64
#define BATCH     2
#define SEQ       2048
#define ROWS_TOT  4096
#define KT_TOT    48                       // 768 / 16 (k16 tiles)
#define AWORDS    (ROWS_TOT * MODEL_DIM / 2)   // 1572864 u32 (bf16x2 packed)
#define WWORDS    (MODEL_DIM * MODEL_DIM / 2)  // 294912

// ---------------------------------------------------------------------------
// Scratch (__device__ globals)
// ---------------------------------------------------------------------------
__device__ uint32_t g_inh[3][AWORDS], g_inl[3][AWORDS];  // inputs, A-frag
__device__ uint32_t g_wh[4][WWORDS],  g_wl[4][WWORDS];   // weights, B-frag
__device__ uint32_t g_qh[AWORDS], g_ql[AWORDS];          // Q attn A-frag
__device__ uint32_t g_kh[AWORDS], g_kl[AWORDS];          // K attn B-frag
__device__ uint32_t g_vh[AWORDS], g_vl[AWORDS];          // V attn B-frag
__device__ uint32_t g_ch[AWORDS], g_cl[AWORDS];          // ctx A-frag
__device__ float    g_linv[BATCH * N_HEAD * SEQ];

// ---------------------------------------------------------------------------
// bf16 split helpers
// ---------------------------------------------------------------------------
__device__ __forceinline__ uint32_t bfround(float x) {
    return __float_as_uint(x) + 0x8000u;
}
__device__ __forceinline__ void split2(float x0, float x1,
                                       uint32_t& hw, uint32_t& lw) {
    uint32_t h0 = bfround(x0) & 0xFFFF0000u;
    uint32_t h1 = bfround(x1) & 0xFFFF0000u;
    float l0 = x0 - __uint_as_float(h0);
    float l1 = x1 - __uint_as_float(h1);
    hw = (h0 >> 16) | h1;
    lw = (bfround(l0) >> 16) | (bfround(l1) & 0xFFFF0000u);
}

// mma m16n8k16 bf16: D += A*B
__device__ __forceinline__ void mma1(float* d, const uint4& a, const uint2& b) {
    asm volatile(
        "mma.sync.aligned.m16n8k16.row.col.f32.bf16.bf16.f32 "
        "{%0,%1,%2,%3},{%4,%5,%6,%7},{%8,%9},{%0,%1,%2,%3};"
        : "+f"(d[0]), "+f"(d[1]), "+f"(d[2]), "+f"(d[3])
        : "r"(a.x), "r"(a.y), "r"(a.z), "r"(a.w), "r"(b.x), "r"(b.y));
}
__device__ __forceinline__ void mma3(float* d, const uint4& ah, const uint4& al,
                                     const uint2& bh, const uint2& bl) {
    mma1(d, ah, bh); mma1(d, ah, bl); mma1(d, al, bh);
}
__device__ __forceinline__ void cpa16(uint32_t s, const void* g) {
    asm volatile("cp.async.ca.shared.global [%0], [%1], 16;" :: "r"(s), "l"(g));
}
#define CP_COMMIT() asm volatile("cp.async.commit_group;")
#define CP_WAIT0()  asm volatile("cp.async.wait_group 0;")
#define CP_WAIT1()  asm volatile("cp.async.wait_group 1;")

// Fragment word indexing (bf16x2):
// Q: [b*h][qblk16][kt4][mt8][128]   (m=s, k=d)
__device__ __forceinline__ size_t q_idx(int R, int C) {
    int b = R >> 11, s = R & 2047, h = C >> 6, d = C & 63;
    size_t tile = (((size_t)(b * N_HEAD + h) * 16 + (s >> 7)) * 4 + (d >> 4)) * 8
                  + ((s & 127) >> 4);
    return tile * 128 + ((((s & 7) << 2) | ((d & 7) >> 1)) << 2)
           + ((s >> 3) & 1) + (((d >> 3) & 1) << 1);
}
// K: [b*h][chunk32][kt4(d)][nt8(key)][64]
__device__ __forceinline__ size_t k_idx(int R, int C) {
    int b = R >> 11, s = R & 2047, h = C >> 6, d = C & 63;
    size_t tile = (((size_t)(b * N_HEAD + h) * 32 + (s >> 6)) * 4 + (d >> 4)) * 8
                  + ((s & 63) >> 3);
    return tile * 64 + ((((s & 7) << 2) | ((d & 7) >> 1)) << 1) + ((d >> 3) & 1);
}
// V: [b*h][chunk32][kt4(key)][nt8(d)][64]  (pair along s; R even)
__device__ __forceinline__ size_t v_idx(int R, int C) {
    int b = R >> 11, s = R & 2047, h = C >> 6, d = C & 63;
    size_t tile = (((size_t)(b * N_HEAD + h) * 32 + (s >> 6)) * 4 + ((s & 63) >> 4)) * 8
                  + (d >> 3);
    return tile * 64 + ((((d & 7) << 2) | ((s & 7) >> 1)) << 1) + ((s >> 3) & 1);
}
// ctx / inputs: [rowblk32][kt48][mt8][128]
__device__ __forceinline__ size_t c_idx(int R, int C) {
    size_t tile = ((size_t)(R >> 7) * KT_TOT + (C >> 4)) * 8 + ((R & 127) >> 4);
    return tile * 128 + ((((R & 7) << 2) | ((C & 7) >> 1)) << 2)
           + ((R >> 3) & 1) + (((C >> 3) & 1) << 1);
}

// ---------------------------------------------------------------------------
// Prep kernels
// ---------------------------------------------------------------------------
__global__ __launch_bounds__(256) void prep_a_kernel(
    const float* __restrict__ X, uint32_t* __restrict__ Ah, uint32_t* __restrict__ Al) {
    int id = blockIdx.x * 256 + threadIdx.x;        // AWORDS
    int wd = id & 127, tile = id >> 7;
    int mt = tile & 7, kt = (tile >> 3) % KT_TOT, rb = tile / (KT_TOT * 8);
    int lane = wd >> 2, slot = wd & 3;
    int r = rb * 128 + mt * 16 + (slot & 1) * 8 + (lane >> 2);
    int k = kt * 16 + ((slot >> 1) & 1) * 8 + (lane & 3) * 2;
    float x0 = X[(size_t)r * MODEL_DIM + k];
    float x1 = X[(size_t)r * MODEL_DIM + k + 1];
    uint32_t hw, lw; split2(x0, x1, hw, lw);
    Ah[id] = hw; Al[id] = lw;
}

__global__ __launch_bounds__(256) void prep_b_kernel(
    const float* __restrict__ W, uint32_t* __restrict__ Bh, uint32_t* __restrict__ Bl) {
    int id = blockIdx.x * 256 + threadIdx.x;        // WWORDS
    int wd = id & 63, tile = id >> 6;
    int nt = tile & 15, kt = (tile >> 4) % KT_TOT, cb = tile / (KT_TOT * 16);
    int lane = wd >> 1, slot = wd & 1;
    int n = cb * 128 + nt * 8 + (lane >> 2);
    int k = kt * 16 + slot * 8 + (lane & 3) * 2;
    float x0 = W[(size_t)n * MODEL_DIM + k];
    float x1 = W[(size_t)n * MODEL_DIM + k + 1];
    uint32_t hw, lw; split2(x0, x1, hw, lw);
    Bh[id] = hw; Bl[id] = lw;
}

// ---------------------------------------------------------------------------
// Projection GEMM (split-bf16 frags). Block 128x128, k=32/iter, 2-stage.
// mode 0=Q(*0.125), 1=K, 2=V, 3=fp32 out.  cb0 = column-block offset.
// ---------------------------------------------------------------------------
__global__ __launch_bounds__(256) void proj_kernel(
    const uint32_t* __restrict__ Ah, const uint32_t* __restrict__ Al,
    const uint32_t* __restrict__ Bh, const uint32_t* __restrict__ Bl,
    const float* __restrict__ bias, float* __restrict__ outF,
    uint32_t* __restrict__ oh, uint32_t* __restrict__ ol, int mode, int cb0) {
    extern __shared__ uint32_t S[];   // [stage2][arr4][2048]
    const int tid = threadIdx.x;
    const int lane = tid & 31;
    const int w = tid >> 5;
    const int g = lane >> 2;
    const int t = lane & 3;
    const int cb = blockIdx.x + cb0;
    const int rb = blockIdx.y;
    const int m0 = (w >> 2) * 64;
    const int n0 = (w & 3) * 32;
    const int bm = rb * 128, bn = cb * 128;

    uint32_t sbase = (uint32_t)__cvta_generic_to_shared(S);

    auto issue = [&](int st, int it) {
        size_t aoff = ((size_t)rb * KT_TOT + it * 2) * 1024;
        size_t boff = ((size_t)cb * KT_TOT + it * 2) * 1024;
        const uint32_t* src[4] = {Ah + aoff, Al + aoff, Bh + boff, Bl + boff};
#pragma unroll
        for (int a = 0; a < 4; a++) {
            uint32_t dst = sbase + ((st * 4 + a) * 2048) * 4;
#pragma unroll
            for (int u = 0; u < 2; u++) {
                int e = (tid + u * 256) * 4;
                cpa16(dst + e * 4, src[a] + e);
            }
        }
        CP_COMMIT();
    };

    float acc[4][4][4] = {};
    issue(0, 0);

    for (int it = 0; it < KT_TOT / 2; it++) {
        int st = it & 1;
        CP_WAIT0();
        __syncthreads();
        if (it + 1 < KT_TOT / 2) issue(st ^ 1, it + 1);
        const uint32_t* sAh = S + (st * 4 + 0) * 2048;
        const uint32_t* sAl = S + (st * 4 + 1) * 2048;
        const uint32_t* sBh = S + (st * 4 + 2) * 2048;
        const uint32_t* sBl = S + (st * 4 + 3) * 2048;
#pragma unroll
        for (int kk = 0; kk < 2; kk++) {
            uint4 ah[4], al[4];
            uint2 bh[4], bl[4];
#pragma unroll
            for (int i = 0; i < 4; i++) {
                int idx = (kk * 8 + (m0 >> 4) + i) * 32 + lane;
                ah[i] = ((const uint4*)sAh)[idx];
                al[i] = ((const uint4*)sAl)[idx];
            }
#pragma unroll
            for (int j = 0; j < 4; j++) {
                int idx = (kk * 16 + (n0 >> 3) + j) * 32 + lane;
                bh[j] = ((const uint2*)sBh)[idx];
                bl[j] = ((const uint2*)sBl)[idx];
            }
#pragma unroll
            for (int i = 0; i < 4; i++)
#pragma unroll
                for (int j = 0; j < 4; j++)
                    mma3(acc[i][j], ah[i], al[i], bh[j], bl[j]);
        }
        __syncthreads();
    }

    // epilogue
#pragma unroll
    for (int j = 0; j < 4; j++) {
        int c0 = bn + n0 + j * 8 + t * 2;
        float b0 = __ldg(&bias[c0]);
        float b1 = __ldg(&bias[c0 + 1]);
#pragma unroll
        for (int i = 0; i < 4; i++) {
            int r0 = bm + m0 + i * 16 + g;
            float sc = (mode == 0) ? 0.125f : 1.0f;
            float v00 = (acc[i][j][0] + b0) * sc, v01 = (acc[i][j][1] + b1) * sc;
            float v10 = (acc[i][j][2] + b0) * sc, v11 = (acc[i][j][3] + b1) * sc;
            if (mode == 3) {
                *(float2*)&outF[(size_t)r0 * MODEL_DIM + c0] = make_float2(v00, v01);
                *(float2*)&outF[(size_t)(r0 + 8) * MODEL_DIM + c0] = make_float2(v10, v11);
            } else if (mode == 2) {
                float p00 = __shfl_down_sync(0xffffffffu, v00, 4);
                float p01 = __shfl_down_sync(0xffffffffu, v01, 4);
                float p10 = __shfl_down_sync(0xffffffffu, v10, 4);
                float p11 = __shfl_down_sync(0xffffffffu, v11, 4);
                if (!(g & 1)) {
                    uint32_t hw, lw; size_t ix;
                    split2(v00, p00, hw, lw); ix = v_idx(r0, c0);         oh[ix] = hw; ol[ix] = lw;
                    split2(v01, p01, hw, lw); ix = v_idx(r0, c0 + 1);     oh[ix] = hw; ol[ix] = lw;
                    split2(v10, p10, hw, lw); ix = v_idx(r0 + 8, c0);     oh[ix] = hw; ol[ix] = lw;
                    split2(v11, p11, hw, lw); ix = v_idx(r0 + 8, c0 + 1); oh[ix] = hw; ol[ix] = lw;
                }
            } else {
                uint32_t hw, lw; size_t ix;
                split2(v00, v01, hw, lw);
                ix = (mode == 0) ? q_idx(r0, c0) : k_idx(r0, c0);
                oh[ix] = hw; ol[ix] = lw;
                split2(v10, v11, hw, lw);
                ix = (mode == 0) ? q_idx(r0 + 8, c0) : k_idx(r0 + 8, c0);
                oh[ix] = hw; ol[ix] = lw;
            }
        }
    }
}

// ---------------------------------------------------------------------------
// Attention. grid (16, heads_in_slice, 2), 256 thr; h = h0 + blockIdx.y.
// Warp = 16 q-rows x all 64 keys; score accs ARE the W A-frags.
// ---------------------------------------------------------------------------
#define QH_OFF 0
#define QL_OFF 4096
#define KV_OFF 8192      // stage st: +st*8192; KH+0 KL+2048 VH+4096 VL+6144
#define ATTN_SMEM (24576 * 4)    // 98304 B

__global__ __launch_bounds__(256, 2) void attn_kernel(
    const uint32_t* __restrict__ qh, const uint32_t* __restrict__ ql,
    const uint32_t* __restrict__ kh, const uint32_t* __restrict__ kl,
    const uint32_t* __restrict__ vh, const uint32_t* __restrict__ vl,
    float* __restrict__ attn, uint32_t* __restrict__ ch, uint32_t* __restrict__ cl,
    float* __restrict__ linv_out, int h0) {
    extern __shared__ uint32_t sm[];

    const int tid = threadIdx.x;
    const int lane = tid & 31;
    const int w = tid >> 5;
    const int g = lane >> 2;
    const int t = lane & 3;
    const int b = blockIdx.z;
    const int h = h0 + blockIdx.y;
    const int q0 = blockIdx.x * 128;

    uint32_t sbase = (uint32_t)__cvta_generic_to_shared(sm);

    auto issue_kv = [&](int st, int kc) {
        size_t base = ((size_t)(b * N_HEAD + h) * 32 + kc) * 2048;
        const uint32_t* src[4] = {kh + base, kl + base, vh + base, vl + base};
#pragma unroll
        for (int a = 0; a < 4; a++) {
            uint32_t dst = sbase + (KV_OFF + st * 8192 + a * 2048) * 4;
#pragma unroll
            for (int u = 0; u < 2; u++) {
                int e = (tid + u * 256) * 4;
                cpa16(dst + e * 4, src[a] + e);
            }
        }
        CP_COMMIT();
    };

    issue_kv(0, 0);

    {
        size_t qb = ((size_t)(b * N_HEAD + h) * 16 + (q0 >> 7)) * 4096;
#pragma unroll
        for (int u = 0; u < 4; u++) {
            int e = tid + u * 256;
            ((uint4*)(sm + QH_OFF))[e] = ((const uint4*)(qh + qb))[e];
            ((uint4*)(sm + QL_OFF))[e] = ((const uint4*)(ql + qb))[e];
        }
    }

    float l0 = 0.f, l1 = 0.f;
    float ctx[8][4] = {};

    const int r0g = q0 + w * 16 + g;
    const size_t arow = ((size_t)((b * N_HEAD + h) * SEQ) + r0g) * SEQ;

    for (int kc = 0; kc < SEQ / 64; kc++) {
        const int c0 = kc * 64;
        const int st = kc & 1;
        __syncthreads();
        if (kc + 1 < SEQ / 64) { issue_kv(st ^ 1, kc + 1); CP_WAIT1(); }
        else                   { CP_WAIT0(); }
        __syncthreads();

        const uint32_t* sKH = sm + KV_OFF + st * 8192;
        const uint32_t* sKL = sKH + 2048;
        const uint32_t* sVH = sKH + 4096;
        const uint32_t* sVL = sKH + 6144;

        float s[8][4] = {};
#pragma unroll
        for (int kk = 0; kk < 4; kk++) {
            uint4 ah = ((const uint4*)(sm + QH_OFF))[(kk * 8 + w) * 32 + lane];
            uint4 al = ((const uint4*)(sm + QL_OFF))[(kk * 8 + w) * 32 + lane];
#pragma unroll
            for (int j = 0; j < 8; j++) {
                uint2 bh = ((const uint2*)sKH)[(kk * 8 + j) * 32 + lane];
                uint2 bl = ((const uint2*)sKL)[(kk * 8 + j) * 32 + lane];
                mma3(s[j], ah, al, bh, bl);
            }
        }

#pragma unroll
        for (int kk = 0; kk < 4; kk++) {
            uint4 wah, wal;
            {
                int j = kk * 2;
                float e0 = __expf(s[j][0]);
                float e1 = __expf(s[j][1]);
                float e2 = __expf(s[j][2]);
                float e3 = __expf(s[j][3]);
                l0 += e0 + e1; l1 += e2 + e3;
                size_t ab = arow + c0 + j * 8 + t * 2;
                *(float2*)(attn + ab) = make_float2(e0, e1);
                *(float2*)(attn + ab + (size_t)8 * SEQ) = make_float2(e2, e3);
                split2(e0, e1, wah.x, wal.x);
                split2(e2, e3, wah.y, wal.y);
                j = kk * 2 + 1;
                e0 = __expf(s[j][0]); e1 = __expf(s[j][1]);
                e2 = __expf(s[j][2]); e3 = __expf(s[j][3]);
                l0 += e0 + e1; l1 += e2 + e3;
                ab = arow + c0 + j * 8 + t * 2;
                *(float2*)(attn + ab) = make_float2(e0, e1);
                *(float2*)(attn + ab + (size_t)8 * SEQ) = make_float2(e2, e3);
                split2(e0, e1, wah.z, wal.z);
                split2(e2, e3, wah.w, wal.w);
            }
#pragma unroll
            for (int j = 0; j < 8; j++) {
                uint2 bh = ((const uint2*)sVH)[(kk * 8 + j) * 32 + lane];
                uint2 bl = ((const uint2*)sVL)[(kk * 8 + j) * 32 + lane];
                mma3(ctx[j], wah, wal, bh, bl);
            }
        }
    }

    l0 += __shfl_xor_sync(0xffffffffu, l0, 1);
    l0 += __shfl_xor_sync(0xffffffffu, l0, 2);
    l1 += __shfl_xor_sync(0xffffffffu, l1, 1);
    l1 += __shfl_xor_sync(0xffffffffu, l1, 2);
    float ri0 = 1.0f / l0;
    float ri1 = 1.0f / l1;

    if (t == 0) {
        size_t lb = (size_t)(b * N_HEAD + h) * SEQ + q0 + w * 16 + g;
        linv_out[lb] = ri0;
        linv_out[lb + 8] = ri1;
    }

#pragma unroll
    for (int j = 0; j < 8; j++) {
        int C0 = h * HEAD_DIM + j * 8 + t * 2;
        int R0 = b * SEQ + q0 + w * 16 + g;
        uint32_t hw, lw; size_t ix;
        split2(ctx[j][0] * ri0, ctx[j][1] * ri0, hw, lw);
        ix = c_idx(R0, C0); ch[ix] = hw; cl[ix] = lw;
        split2(ctx[j][2] * ri1, ctx[j][3] * ri1, hw, lw);
        ix = c_idx(R0 + 8, C0); ch[ix] = hw; cl[ix] = lw;
    }
}

// ---------------------------------------------------------------------------
// Normalize weights by per-row 1/l. grid (4096, heads_in_slice, 2), h = h0+y.
// ---------------------------------------------------------------------------
__global__ __launch_bounds__(256) void norm_kernel(
    float* __restrict__ attn, const float* __restrict__ linv, int h0) {
    const int bh = blockIdx.z * N_HEAD + h0 + blockIdx.y;
    const size_t loc = (size_t)blockIdx.x * 256 + threadIdx.x;   // < 2048*2048/4
    float r = __ldg(&linv[(size_t)bh * SEQ + (loc >> 9)]);
    float4* p = ((float4*)attn) + ((size_t)bh << 20) + loc;
    float4 v = *p;
    v.x *= r; v.y *= r; v.z *= r; v.w *= r;
    *p = v;
}

// ---------------------------------------------------------------------------
// Launch — forked graph with sliced attn/norm overlap:
//  s0: prepA(q) prepB(wq)[epq] projQ(h0-5) | attnA[eaA] attnB[eaB] projO ...
//  s1: prepA(k) prepB(wk) projK(h0-5)[ek1] projK(h6-11)[ek2] | normA[enA]
//  s2: prepA(v) prepB(wv) projV(h0-5)[ev1] projV(h6-11)[ev2] | normB[enB]
//  s3: prepB(wo)[ewo] (waits epq) projQ(h6-11)[eq2]
// ---------------------------------------------------------------------------
extern "C" void kernel_launch(void* const* d_in, const int* in_sizes, int n_in,
                              void* d_out, int out_size) {
    const float* in_x[3] = {(const float*)d_in[0], (const float*)d_in[1], (const float*)d_in[2]};
    const float* w_w[4]  = {(const float*)d_in[3], (const float*)d_in[5], (const float*)d_in[7],
                            (const float*)d_in[9]};
    const float* w_b[4]  = {(const float*)d_in[4], (const float*)d_in[6], (const float*)d_in[8],
                            (const float*)d_in[10]};

    uint32_t *inh[3], *inl[3], *wh[4], *wl[4];
    uint32_t *qh, *ql, *kh, *kl, *vh, *vl, *ch, *cl;
    float* linv;
    {
        uint32_t* base;
        cudaGetSymbolAddress((void**)&base, g_inh);
        for (int i = 0; i < 3; i++) inh[i] = base + (size_t)i * AWORDS;
        cudaGetSymbolAddress((void**)&base, g_inl);
        for (int i = 0; i < 3; i++) inl[i] = base + (size_t)i * AWORDS;
        cudaGetSymbolAddress((void**)&base, g_wh);
        for (int i = 0; i < 4; i++) wh[i] = base + (size_t)i * WWORDS;
        cudaGetSymbolAddress((void**)&base, g_wl);
        for (int i = 0; i < 4; i++) wl[i] = base + (size_t)i * WWORDS;
    }
    cudaGetSymbolAddress((void**)&qh, g_qh); cudaGetSymbolAddress((void**)&ql, g_ql);
    cudaGetSymbolAddress((void**)&kh, g_kh); cudaGetSymbolAddress((void**)&kl, g_kl);
    cudaGetSymbolAddress((void**)&vh, g_vh); cudaGetSymbolAddress((void**)&vl, g_vl);
    cudaGetSymbolAddress((void**)&ch, g_ch); cudaGetSymbolAddress((void**)&cl, g_cl);
    cudaGetSymbolAddress((void**)&linv, g_linv);

    float* out  = (float*)d_out;
    float* attn = out + (size_t)BATCH * SEQ * MODEL_DIM;

    static cudaStream_t s1, s2, s3;
    static cudaEvent_t e0, epq, eq2, ek1, ek2, ev1, ev2, ewo, eaA, eaB, enA, enB;
    static bool init_done = false;
    if (!init_done) {
        cudaFuncSetAttribute(proj_kernel, cudaFuncAttributeMaxDynamicSharedMemorySize, 65536);
        cudaFuncSetAttribute(attn_kernel, cudaFuncAttributeMaxDynamicSharedMemorySize, ATTN_SMEM);
        cudaStreamCreateWithFlags(&s1, cudaStreamNonBlocking);
        cudaStreamCreateWithFlags(&s2, cudaStreamNonBlocking);
        cudaStreamCreateWithFlags(&s3, cudaStreamNonBlocking);
        cudaEvent_t* evs[12] = {&e0, &epq, &eq2, &ek1, &ek2, &ev1,
                                &ev2, &ewo, &eaA, &eaB, &enA, &enB};
        for (int i = 0; i < 12; i++)
            cudaEventCreateWithFlags(evs[i], cudaEventDisableTiming);
        init_done = true;
    }

    cudaStream_t s0 = 0;
    dim3 hgrid(3, ROWS_TOT / 128);     // half-projection: col blocks {cb0..cb0+2}

    // fork
    cudaEventRecord(e0, s0);
    cudaStreamWaitEvent(s1, e0, 0);
    cudaStreamWaitEvent(s2, e0, 0);
    cudaStreamWaitEvent(s3, e0, 0);

    // s0: Q chain (first half only; second half on s3)
    prep_a_kernel<<<AWORDS / 256, 256, 0, s0>>>(in_x[0], inh[0], inl[0]);
    prep_b_kernel<<<WWORDS / 256, 256, 0, s0>>>(w_w[0], wh[0], wl[0]);
    cudaEventRecord(epq, s0);
    proj_kernel<<<hgrid, 256, 65536, s0>>>(inh[0], inl[0], wh[0], wl[0], w_b[0],
                                           nullptr, qh, ql, 0, 0);
    // s3: wo prep + Q second half
    prep_b_kernel<<<WWORDS / 256, 256, 0, s3>>>(w_w[3], wh[3], wl[3]);
    cudaEventRecord(ewo, s3);
    cudaStreamWaitEvent(s3, epq, 0);
    proj_kernel<<<hgrid, 256, 65536, s3>>>(inh[0], inl[0], wh[0], wl[0], w_b[0],
                                           nullptr, qh, ql, 0, 3);
    cudaEventRecord(eq2, s3);

    // s1: K chain (two halves)
    prep_a_kernel<<<AWORDS / 256, 256, 0, s1>>>(in_x[1], inh[1], inl[1]);
    prep_b_kernel<<<WWORDS / 256, 256, 0, s1>>>(w_w[1], wh[1], wl[1]);
    proj_kernel<<<hgrid, 256, 65536, s1>>>(inh[1], inl[1], wh[1], wl[1], w_b[1],
                                           nullptr, kh, kl, 1, 0);
    cudaEventRecord(ek1, s1);
    proj_kernel<<<hgrid, 256, 65536, s1>>>(inh[1], inl[1], wh[1], wl[1], w_b[1],
                                           nullptr, kh, kl, 1, 3);
    cudaEventRecord(ek2, s1);

    // s2: V chain (two halves)
    prep_a_kernel<<<AWORDS / 256, 256, 0, s2>>>(in_x[2], inh[2], inl[2]);
    prep_b_kernel<<<WWORDS / 256, 256, 0, s2>>>(w_w[2], wh[2], wl[2]);
    proj_kernel<<<hgrid, 256, 65536, s2>>>(inh[2], inl[2], wh[2], wl[2], w_b[2],
                                           nullptr, vh, vl, 2, 0);
    cudaEventRecord(ev1, s2);
    proj_kernel<<<hgrid, 256, 65536, s2>>>(inh[2], inl[2], wh[2], wl[2], w_b[2],
                                           nullptr, vh, vl, 2, 3);
    cudaEventRecord(ev2, s2);

    // attn slice A (heads 0-5): needs Q/K/V first halves only
    cudaStreamWaitEvent(s0, ek1, 0);
    cudaStreamWaitEvent(s0, ev1, 0);
    attn_kernel<<<dim3(SEQ / 128, 6, BATCH), 256, ATTN_SMEM, s0>>>(
        qh, ql, kh, kl, vh, vl, attn, ch, cl, linv, 0);
    cudaEventRecord(eaA, s0);

    // attn slice B (heads 6-11): needs everything
    cudaStreamWaitEvent(s0, eq2, 0);
    cudaStreamWaitEvent(s0, ek2, 0);
    cudaStreamWaitEvent(s0, ev2, 0);
    attn_kernel<<<dim3(SEQ / 128, 6, BATCH), 256, ATTN_SMEM, s0>>>(
        qh, ql, kh, kl, vh, vl, attn, ch, cl, linv, 6);
    cudaEventRecord(eaB, s0);

    // normA overlaps attnB (s1), normB overlaps projO (s2)
    cudaStreamWaitEvent(s1, eaA, 0);
    norm_kernel<<<dim3(4096, 6, BATCH), 256, 0, s1>>>(attn, linv, 0);
    cudaEventRecord(enA, s1);
    cudaStreamWaitEvent(s2, eaB, 0);
    norm_kernel<<<dim3(4096, 6, BATCH), 256, 0, s2>>>(attn, linv, 6);
    cudaEventRecord(enB, s2);

    // s0: output projection (full width)
    cudaStreamWaitEvent(s0, ewo, 0);
    proj_kernel<<<dim3(6, ROWS_TOT / 128), 256, 65536, s0>>>(
        ch, cl, wh[3], wl[3], w_b[3], out, nullptr, nullptr, 3, 0);

    // join
    cudaStreamWaitEvent(s0, enA, 0);
    cudaStreamWaitEvent(s0, enB, 0);
}

// round 14
// speedup vs baseline: 1.0852x; 1.0852x over previous
#include <cuda_runtime.h>
#include <cstdint>
#include <cstddef>

#define MODEL_DIM 768
#define N_HEAD    12
#define HEAD_DIM  64
#define BATCH     2
#define SEQ       2048
#define ROWS_TOT  4096
#define KT_TOT    48                       // 768 / 16 (k16 tiles)
#define AWORDS    (ROWS_TOT * MODEL_DIM / 2)   // 1572864 u32 (bf16x2 packed)
#define WWORDS    (MODEL_DIM * MODEL_DIM / 2)  // 294912

// ---------------------------------------------------------------------------
// Scratch (__device__ globals)
// ---------------------------------------------------------------------------
__device__ uint32_t g_inh[3][AWORDS], g_inl[3][AWORDS];  // inputs, A-frag
__device__ uint32_t g_wh[4][WWORDS],  g_wl[4][WWORDS];   // weights, B-frag
__device__ uint32_t g_qh[AWORDS], g_ql[AWORDS];          // Q attn A-frag
__device__ uint32_t g_kh[AWORDS], g_kl[AWORDS];          // K attn B-frag
__device__ uint32_t g_vh[AWORDS], g_vl[AWORDS];          // V attn B-frag
__device__ uint32_t g_ch[AWORDS], g_cl[AWORDS];          // ctx A-frag
__device__ float    g_linv[BATCH * N_HEAD * SEQ];

// ---------------------------------------------------------------------------
// bf16 split helpers
// ---------------------------------------------------------------------------
__device__ __forceinline__ uint32_t bfround(float x) {
    return __float_as_uint(x) + 0x8000u;
}
__device__ __forceinline__ void split2(float x0, float x1,
                                       uint32_t& hw, uint32_t& lw) {
    uint32_t h0 = bfround(x0) & 0xFFFF0000u;
    uint32_t h1 = bfround(x1) & 0xFFFF0000u;
    float l0 = x0 - __uint_as_float(h0);
    float l1 = x1 - __uint_as_float(h1);
    hw = (h0 >> 16) | h1;
    lw = (bfround(l0) >> 16) | (bfround(l1) & 0xFFFF0000u);
}

// mma m16n8k16 bf16: D += A*B
__device__ __forceinline__ void mma1(float* d, const uint4& a, const uint2& b) {
    asm volatile(
        "mma.sync.aligned.m16n8k16.row.col.f32.bf16.bf16.f32 "
        "{%0,%1,%2,%3},{%4,%5,%6,%7},{%8,%9},{%0,%1,%2,%3};"
        : "+f"(d[0]), "+f"(d[1]), "+f"(d[2]), "+f"(d[3])
        : "r"(a.x), "r"(a.y), "r"(a.z), "r"(a.w), "r"(b.x), "r"(b.y));
}
__device__ __forceinline__ void mma3(float* d, const uint4& ah, const uint4& al,
                                     const uint2& bh, const uint2& bl) {
    mma1(d, ah, bh); mma1(d, ah, bl); mma1(d, al, bh);
}
__device__ __forceinline__ void cpa16(uint32_t s, const void* g) {
    asm volatile("cp.async.ca.shared.global [%0], [%1], 16;" :: "r"(s), "l"(g));
}
#define CP_COMMIT() asm volatile("cp.async.commit_group;")
#define CP_WAIT0()  asm volatile("cp.async.wait_group 0;")
#define CP_WAIT1()  asm volatile("cp.async.wait_group 1;")

// Fragment word indexing (bf16x2):
// Q: [b*h][qblk16][kt4][mt8][128]   (m=s, k=d)
__device__ __forceinline__ size_t q_idx(int R, int C) {
    int b = R >> 11, s = R & 2047, h = C >> 6, d = C & 63;
    size_t tile = (((size_t)(b * N_HEAD + h) * 16 + (s >> 7)) * 4 + (d >> 4)) * 8
                  + ((s & 127) >> 4);
    return tile * 128 + ((((s & 7) << 2) | ((d & 7) >> 1)) << 2)
           + ((s >> 3) & 1) + (((d >> 3) & 1) << 1);
}
// K: [b*h][chunk32][kt4(d)][nt8(key)][64]
__device__ __forceinline__ size_t k_idx(int R, int C) {
    int b = R >> 11, s = R & 2047, h = C >> 6, d = C & 63;
    size_t tile = (((size_t)(b * N_HEAD + h) * 32 + (s >> 6)) * 4 + (d >> 4)) * 8
                  + ((s & 63) >> 3);
    return tile * 64 + ((((s & 7) << 2) | ((d & 7) >> 1)) << 1) + ((d >> 3) & 1);
}
// V: [b*h][chunk32][kt4(key)][nt8(d)][64]  (pair along s; R even)
__device__ __forceinline__ size_t v_idx(int R, int C) {
    int b = R >> 11, s = R & 2047, h = C >> 6, d = C & 63;
    size_t tile = (((size_t)(b * N_HEAD + h) * 32 + (s >> 6)) * 4 + ((s & 63) >> 4)) * 8
                  + (d >> 3);
    return tile * 64 + ((((d & 7) << 2) | ((s & 7) >> 1)) << 1) + ((s >> 3) & 1);
}
// ctx / inputs: [rowblk32][kt48][mt8][128]
__device__ __forceinline__ size_t c_idx(int R, int C) {
    size_t tile = ((size_t)(R >> 7) * KT_TOT + (C >> 4)) * 8 + ((R & 127) >> 4);
    return tile * 128 + ((((R & 7) << 2) | ((C & 7) >> 1)) << 2)
           + ((R >> 3) & 1) + (((C >> 3) & 1) << 1);
}

// ---------------------------------------------------------------------------
// Prep kernels
// ---------------------------------------------------------------------------
__global__ __launch_bounds__(256) void prep_a_kernel(
    const float* __restrict__ X, uint32_t* __restrict__ Ah, uint32_t* __restrict__ Al) {
    int id = blockIdx.x * 256 + threadIdx.x;        // AWORDS
    int wd = id & 127, tile = id >> 7;
    int mt = tile & 7, kt = (tile >> 3) % KT_TOT, rb = tile / (KT_TOT * 8);
    int lane = wd >> 2, slot = wd & 3;
    int r = rb * 128 + mt * 16 + (slot & 1) * 8 + (lane >> 2);
    int k = kt * 16 + ((slot >> 1) & 1) * 8 + (lane & 3) * 2;
    float x0 = X[(size_t)r * MODEL_DIM + k];
    float x1 = X[(size_t)r * MODEL_DIM + k + 1];
    uint32_t hw, lw; split2(x0, x1, hw, lw);
    Ah[id] = hw; Al[id] = lw;
}

__global__ __launch_bounds__(256) void prep_b_kernel(
    const float* __restrict__ W, uint32_t* __restrict__ Bh, uint32_t* __restrict__ Bl) {
    int id = blockIdx.x * 256 + threadIdx.x;        // WWORDS
    int wd = id & 63, tile = id >> 6;
    int nt = tile & 15, kt = (tile >> 4) % KT_TOT, cb = tile / (KT_TOT * 16);
    int lane = wd >> 1, slot = wd & 1;
    int n = cb * 128 + nt * 8 + (lane >> 2);
    int k = kt * 16 + slot * 8 + (lane & 3) * 2;
    float x0 = W[(size_t)n * MODEL_DIM + k];
    float x1 = W[(size_t)n * MODEL_DIM + k + 1];
    uint32_t hw, lw; split2(x0, x1, hw, lw);
    Bh[id] = hw; Bl[id] = lw;
}

// ---------------------------------------------------------------------------
// Projection GEMM (split-bf16 frags). Block 128x128, k=32/iter, 2-stage.
// mode 0=Q(*0.125), 1=K, 2=V, 3=fp32 out
// ---------------------------------------------------------------------------
__global__ __launch_bounds__(256) void proj_kernel(
    const uint32_t* __restrict__ Ah, const uint32_t* __restrict__ Al,
    const uint32_t* __restrict__ Bh, const uint32_t* __restrict__ Bl,
    const float* __restrict__ bias, float* __restrict__ outF,
    uint32_t* __restrict__ oh, uint32_t* __restrict__ ol, int mode) {
    extern __shared__ uint32_t S[];   // [stage2][arr4][2048]
    const int tid = threadIdx.x;
    const int lane = tid & 31;
    const int w = tid >> 5;
    const int g = lane >> 2;
    const int t = lane & 3;
    const int cb = blockIdx.x;
    const int rb = blockIdx.y;
    const int m0 = (w >> 2) * 64;
    const int n0 = (w & 3) * 32;
    const int bm = rb * 128, bn = cb * 128;

    uint32_t sbase = (uint32_t)__cvta_generic_to_shared(S);

    auto issue = [&](int st, int it) {
        size_t aoff = ((size_t)rb * KT_TOT + it * 2) * 1024;
        size_t boff = ((size_t)cb * KT_TOT + it * 2) * 1024;
        const uint32_t* src[4] = {Ah + aoff, Al + aoff, Bh + boff, Bl + boff};
#pragma unroll
        for (int a = 0; a < 4; a++) {
            uint32_t dst = sbase + ((st * 4 + a) * 2048) * 4;
#pragma unroll
            for (int u = 0; u < 2; u++) {
                int e = (tid + u * 256) * 4;
                cpa16(dst + e * 4, src[a] + e);
            }
        }
        CP_COMMIT();
    };

    float acc[4][4][4] = {};
    issue(0, 0);

    for (int it = 0; it < KT_TOT / 2; it++) {
        int st = it & 1;
        CP_WAIT0();
        __syncthreads();
        if (it + 1 < KT_TOT / 2) issue(st ^ 1, it + 1);
        const uint32_t* sAh = S + (st * 4 + 0) * 2048;
        const uint32_t* sAl = S + (st * 4 + 1) * 2048;
        const uint32_t* sBh = S + (st * 4 + 2) * 2048;
        const uint32_t* sBl = S + (st * 4 + 3) * 2048;
#pragma unroll
        for (int kk = 0; kk < 2; kk++) {
            uint4 ah[4], al[4];
            uint2 bh[4], bl[4];
#pragma unroll
            for (int i = 0; i < 4; i++) {
                int idx = (kk * 8 + (m0 >> 4) + i) * 32 + lane;
                ah[i] = ((const uint4*)sAh)[idx];
                al[i] = ((const uint4*)sAl)[idx];
            }
#pragma unroll
            for (int j = 0; j < 4; j++) {
                int idx = (kk * 16 + (n0 >> 3) + j) * 32 + lane;
                bh[j] = ((const uint2*)sBh)[idx];
                bl[j] = ((const uint2*)sBl)[idx];
            }
#pragma unroll
            for (int i = 0; i < 4; i++)
#pragma unroll
                for (int j = 0; j < 4; j++)
                    mma3(acc[i][j], ah[i], al[i], bh[j], bl[j]);
        }
        __syncthreads();
    }

    // epilogue
#pragma unroll
    for (int j = 0; j < 4; j++) {
        int c0 = bn + n0 + j * 8 + t * 2;
        float b0 = __ldg(&bias[c0]);
        float b1 = __ldg(&bias[c0 + 1]);
#pragma unroll
        for (int i = 0; i < 4; i++) {
            int r0 = bm + m0 + i * 16 + g;
            float sc = (mode == 0) ? 0.125f : 1.0f;
            float v00 = (acc[i][j][0] + b0) * sc, v01 = (acc[i][j][1] + b1) * sc;
            float v10 = (acc[i][j][2] + b0) * sc, v11 = (acc[i][j][3] + b1) * sc;
            if (mode == 3) {
                *(float2*)&outF[(size_t)r0 * MODEL_DIM + c0] = make_float2(v00, v01);
                *(float2*)&outF[(size_t)(r0 + 8) * MODEL_DIM + c0] = make_float2(v10, v11);
            } else if (mode == 2) {
                float p00 = __shfl_down_sync(0xffffffffu, v00, 4);
                float p01 = __shfl_down_sync(0xffffffffu, v01, 4);
                float p10 = __shfl_down_sync(0xffffffffu, v10, 4);
                float p11 = __shfl_down_sync(0xffffffffu, v11, 4);
                if (!(g & 1)) {
                    uint32_t hw, lw; size_t ix;
                    split2(v00, p00, hw, lw); ix = v_idx(r0, c0);         oh[ix] = hw; ol[ix] = lw;
                    split2(v01, p01, hw, lw); ix = v_idx(r0, c0 + 1);     oh[ix] = hw; ol[ix] = lw;
                    split2(v10, p10, hw, lw); ix = v_idx(r0 + 8, c0);     oh[ix] = hw; ol[ix] = lw;
                    split2(v11, p11, hw, lw); ix = v_idx(r0 + 8, c0 + 1); oh[ix] = hw; ol[ix] = lw;
                }
            } else {
                uint32_t hw, lw; size_t ix;
                split2(v00, v01, hw, lw);
                ix = (mode == 0) ? q_idx(r0, c0) : k_idx(r0, c0);
                oh[ix] = hw; ol[ix] = lw;
                split2(v10, v11, hw, lw);
                ix = (mode == 0) ? q_idx(r0 + 8, c0) : k_idx(r0 + 8, c0);
                oh[ix] = hw; ol[ix] = lw;
            }
        }
    }
}

// ---------------------------------------------------------------------------
// Attention. grid (16, heads_in_slice, 2), 256 thr; h = h0 + blockIdx.y.
// Warp = 16 q-rows x all 64 keys; score accs ARE the W A-frags.
// ---------------------------------------------------------------------------
#define QH_OFF 0
#define QL_OFF 4096
#define KV_OFF 8192      // stage st: +st*8192; KH+0 KL+2048 VH+4096 VL+6144
#define ATTN_SMEM (24576 * 4)    // 98304 B

__global__ __launch_bounds__(256, 2) void attn_kernel(
    const uint32_t* __restrict__ qh, const uint32_t* __restrict__ ql,
    const uint32_t* __restrict__ kh, const uint32_t* __restrict__ kl,
    const uint32_t* __restrict__ vh, const uint32_t* __restrict__ vl,
    float* __restrict__ attn, uint32_t* __restrict__ ch, uint32_t* __restrict__ cl,
    float* __restrict__ linv_out, int h0) {
    extern __shared__ uint32_t sm[];

    const int tid = threadIdx.x;
    const int lane = tid & 31;
    const int w = tid >> 5;
    const int g = lane >> 2;
    const int t = lane & 3;
    const int b = blockIdx.z;
    const int h = h0 + blockIdx.y;
    const int q0 = blockIdx.x * 128;

    uint32_t sbase = (uint32_t)__cvta_generic_to_shared(sm);

    auto issue_kv = [&](int st, int kc) {
        size_t base = ((size_t)(b * N_HEAD + h) * 32 + kc) * 2048;
        const uint32_t* src[4] = {kh + base, kl + base, vh + base, vl + base};
#pragma unroll
        for (int a = 0; a < 4; a++) {
            uint32_t dst = sbase + (KV_OFF + st * 8192 + a * 2048) * 4;
#pragma unroll
            for (int u = 0; u < 2; u++) {
                int e = (tid + u * 256) * 4;
                cpa16(dst + e * 4, src[a] + e);
            }
        }
        CP_COMMIT();
    };

    issue_kv(0, 0);

    {
        size_t qb = ((size_t)(b * N_HEAD + h) * 16 + (q0 >> 7)) * 4096;
#pragma unroll
        for (int u = 0; u < 4; u++) {
            int e = tid + u * 256;
            ((uint4*)(sm + QH_OFF))[e] = ((const uint4*)(qh + qb))[e];
            ((uint4*)(sm + QL_OFF))[e] = ((const uint4*)(ql + qb))[e];
        }
    }

    float l0 = 0.f, l1 = 0.f;
    float ctx[8][4] = {};

    const int r0g = q0 + w * 16 + g;
    const size_t arow = ((size_t)((b * N_HEAD + h) * SEQ) + r0g) * SEQ;

    for (int kc = 0; kc < SEQ / 64; kc++) {
        const int c0 = kc * 64;
        const int st = kc & 1;
        __syncthreads();
        if (kc + 1 < SEQ / 64) { issue_kv(st ^ 1, kc + 1); CP_WAIT1(); }
        else                   { CP_WAIT0(); }
        __syncthreads();

        const uint32_t* sKH = sm + KV_OFF + st * 8192;
        const uint32_t* sKL = sKH + 2048;
        const uint32_t* sVH = sKH + 4096;
        const uint32_t* sVL = sKH + 6144;

        float s[8][4] = {};
#pragma unroll
        for (int kk = 0; kk < 4; kk++) {
            uint4 ah = ((const uint4*)(sm + QH_OFF))[(kk * 8 + w) * 32 + lane];
            uint4 al = ((const uint4*)(sm + QL_OFF))[(kk * 8 + w) * 32 + lane];
#pragma unroll
            for (int j = 0; j < 8; j++) {
                uint2 bh = ((const uint2*)sKH)[(kk * 8 + j) * 32 + lane];
                uint2 bl = ((const uint2*)sKL)[(kk * 8 + j) * 32 + lane];
                mma3(s[j], ah, al, bh, bl);
            }
        }

#pragma unroll
        for (int kk = 0; kk < 4; kk++) {
            uint4 wah, wal;
            {
                int j = kk * 2;
                float e0 = __expf(s[j][0]);
                float e1 = __expf(s[j][1]);
                float e2 = __expf(s[j][2]);
                float e3 = __expf(s[j][3]);
                l0 += e0 + e1; l1 += e2 + e3;
                size_t ab = arow + c0 + j * 8 + t * 2;
                *(float2*)(attn + ab) = make_float2(e0, e1);
                *(float2*)(attn + ab + (size_t)8 * SEQ) = make_float2(e2, e3);
                split2(e0, e1, wah.x, wal.x);
                split2(e2, e3, wah.y, wal.y);
                j = kk * 2 + 1;
                e0 = __expf(s[j][0]); e1 = __expf(s[j][1]);
                e2 = __expf(s[j][2]); e3 = __expf(s[j][3]);
                l0 += e0 + e1; l1 += e2 + e3;
                ab = arow + c0 + j * 8 + t * 2;
                *(float2*)(attn + ab) = make_float2(e0, e1);
                *(float2*)(attn + ab + (size_t)8 * SEQ) = make_float2(e2, e3);
                split2(e0, e1, wah.z, wal.z);
                split2(e2, e3, wah.w, wal.w);
            }
#pragma unroll
            for (int j = 0; j < 8; j++) {
                uint2 bh = ((const uint2*)sVH)[(kk * 8 + j) * 32 + lane];
                uint2 bl = ((const uint2*)sVL)[(kk * 8 + j) * 32 + lane];
                mma3(ctx[j], wah, wal, bh, bl);
            }
        }
    }

    l0 += __shfl_xor_sync(0xffffffffu, l0, 1);
    l0 += __shfl_xor_sync(0xffffffffu, l0, 2);
    l1 += __shfl_xor_sync(0xffffffffu, l1, 1);
    l1 += __shfl_xor_sync(0xffffffffu, l1, 2);
    float ri0 = 1.0f / l0;
    float ri1 = 1.0f / l1;

    if (t == 0) {
        size_t lb = (size_t)(b * N_HEAD + h) * SEQ + q0 + w * 16 + g;
        linv_out[lb] = ri0;
        linv_out[lb + 8] = ri1;
    }

#pragma unroll
    for (int j = 0; j < 8; j++) {
        int C0 = h * HEAD_DIM + j * 8 + t * 2;
        int R0 = b * SEQ + q0 + w * 16 + g;
        uint32_t hw, lw; size_t ix;
        split2(ctx[j][0] * ri0, ctx[j][1] * ri0, hw, lw);
        ix = c_idx(R0, C0); ch[ix] = hw; cl[ix] = lw;
        split2(ctx[j][2] * ri1, ctx[j][3] * ri1, hw, lw);
        ix = c_idx(R0 + 8, C0); ch[ix] = hw; cl[ix] = lw;
    }
}

// ---------------------------------------------------------------------------
// Normalize weights by per-row 1/l. grid (4096, heads_in_slice, 2), h = h0+y.
// ---------------------------------------------------------------------------
__global__ __launch_bounds__(256) void norm_kernel(
    float* __restrict__ attn, const float* __restrict__ linv, int h0) {
    const int bh = blockIdx.z * N_HEAD + h0 + blockIdx.y;
    const size_t loc = (size_t)blockIdx.x * 256 + threadIdx.x;   // < 2048*2048/4
    float r = __ldg(&linv[(size_t)bh * SEQ + (loc >> 9)]);
    float4* p = ((float4*)attn) + ((size_t)bh << 20) + loc;
    float4 v = *p;
    v.x *= r; v.y *= r; v.z *= r; v.w *= r;
    *p = v;
}

// ---------------------------------------------------------------------------
// Launch — R11 projection graph + attn/norm slicing only:
//   s0: prepA(q) prepB(wq) projQ ─┐
//   s1: prepA(k) prepB(wk) projK ─┼─ attnA[eaA] attnB[eaB] ── projO ─ join
//   s2: prepA(v) prepB(wv) projV ─┘      │           │
//   s3: prepB(wo)[ewo] ──────────────────┼───────────┼──→ (projO waits ewo)
//   s1: (waits eaA) normA [enA]  ────────┘           │
//   s2: (waits eaB) normB [enB]  ────────────────────┘
// ---------------------------------------------------------------------------
extern "C" void kernel_launch(void* const* d_in, const int* in_sizes, int n_in,
                              void* d_out, int out_size) {
    const float* in_x[3] = {(const float*)d_in[0], (const float*)d_in[1], (const float*)d_in[2]};
    const float* w_w[4]  = {(const float*)d_in[3], (const float*)d_in[5], (const float*)d_in[7],
                            (const float*)d_in[9]};
    const float* w_b[4]  = {(const float*)d_in[4], (const float*)d_in[6], (const float*)d_in[8],
                            (const float*)d_in[10]};

    uint32_t *inh[3], *inl[3], *wh[4], *wl[4];
    uint32_t *qh, *ql, *kh, *kl, *vh, *vl, *ch, *cl;
    float* linv;
    {
        uint32_t* base;
        cudaGetSymbolAddress((void**)&base, g_inh);
        for (int i = 0; i < 3; i++) inh[i] = base + (size_t)i * AWORDS;
        cudaGetSymbolAddress((void**)&base, g_inl);
        for (int i = 0; i < 3; i++) inl[i] = base + (size_t)i * AWORDS;
        cudaGetSymbolAddress((void**)&base, g_wh);
        for (int i = 0; i < 4; i++) wh[i] = base + (size_t)i * WWORDS;
        cudaGetSymbolAddress((void**)&base, g_wl);
        for (int i = 0; i < 4; i++) wl[i] = base + (size_t)i * WWORDS;
    }
    cudaGetSymbolAddress((void**)&qh, g_qh); cudaGetSymbolAddress((void**)&ql, g_ql);
    cudaGetSymbolAddress((void**)&kh, g_kh); cudaGetSymbolAddress((void**)&kl, g_kl);
    cudaGetSymbolAddress((void**)&vh, g_vh); cudaGetSymbolAddress((void**)&vl, g_vl);
    cudaGetSymbolAddress((void**)&ch, g_ch); cudaGetSymbolAddress((void**)&cl, g_cl);
    cudaGetSymbolAddress((void**)&linv, g_linv);

    float* out  = (float*)d_out;
    float* attn = out + (size_t)BATCH * SEQ * MODEL_DIM;

    static cudaStream_t s1, s2, s3;
    static cudaEvent_t e0, ek, ev, ewo, eaA, eaB, enA, enB;
    static bool init_done = false;
    if (!init_done) {
        cudaFuncSetAttribute(proj_kernel, cudaFuncAttributeMaxDynamicSharedMemorySize, 65536);
        cudaFuncSetAttribute(attn_kernel, cudaFuncAttributeMaxDynamicSharedMemorySize, ATTN_SMEM);
        cudaStreamCreateWithFlags(&s1, cudaStreamNonBlocking);
        cudaStreamCreateWithFlags(&s2, cudaStreamNonBlocking);
        cudaStreamCreateWithFlags(&s3, cudaStreamNonBlocking);
        cudaEvent_t* evs[8] = {&e0, &ek, &ev, &ewo, &eaA, &eaB, &enA, &enB};
        for (int i = 0; i < 8; i++)
            cudaEventCreateWithFlags(evs[i], cudaEventDisableTiming);
        init_done = true;
    }

    cudaStream_t s0 = 0;
    dim3 pgrid(MODEL_DIM / 128, ROWS_TOT / 128);   // (6, 32)

    // fork
    cudaEventRecord(e0, s0);
    cudaStreamWaitEvent(s1, e0, 0);
    cudaStreamWaitEvent(s2, e0, 0);
    cudaStreamWaitEvent(s3, e0, 0);

    // s0: Q chain (full width)
    prep_a_kernel<<<AWORDS / 256, 256, 0, s0>>>(in_x[0], inh[0], inl[0]);
    prep_b_kernel<<<WWORDS / 256, 256, 0, s0>>>(w_w[0], wh[0], wl[0]);
    proj_kernel<<<pgrid, 256, 65536, s0>>>(inh[0], inl[0], wh[0], wl[0], w_b[0],
                                           nullptr, qh, ql, 0);
    // s1: K chain
    prep_a_kernel<<<AWORDS / 256, 256, 0, s1>>>(in_x[1], inh[1], inl[1]);
    prep_b_kernel<<<WWORDS / 256, 256, 0, s1>>>(w_w[1], wh[1], wl[1]);
    proj_kernel<<<pgrid, 256, 65536, s1>>>(inh[1], inl[1], wh[1], wl[1], w_b[1],
                                           nullptr, kh, kl, 1);
    cudaEventRecord(ek, s1);
    // s2: V chain
    prep_a_kernel<<<AWORDS / 256, 256, 0, s2>>>(in_x[2], inh[2], inl[2]);
    prep_b_kernel<<<WWORDS / 256, 256, 0, s2>>>(w_w[2], wh[2], wl[2]);
    proj_kernel<<<pgrid, 256, 65536, s2>>>(inh[2], inl[2], wh[2], wl[2], w_b[2],
                                           nullptr, vh, vl, 2);
    cudaEventRecord(ev, s2);
    // s3: wo prep
    prep_b_kernel<<<WWORDS / 256, 256, 0, s3>>>(w_w[3], wh[3], wl[3]);
    cudaEventRecord(ewo, s3);

    // join K,V -> attn slice A (heads 0-5) then slice B (heads 6-11) on s0
    cudaStreamWaitEvent(s0, ek, 0);
    cudaStreamWaitEvent(s0, ev, 0);
    attn_kernel<<<dim3(SEQ / 128, 6, BATCH), 256, ATTN_SMEM, s0>>>(
        qh, ql, kh, kl, vh, vl, attn, ch, cl, linv, 0);
    cudaEventRecord(eaA, s0);
    attn_kernel<<<dim3(SEQ / 128, 6, BATCH), 256, ATTN_SMEM, s0>>>(
        qh, ql, kh, kl, vh, vl, attn, ch, cl, linv, 6);
    cudaEventRecord(eaB, s0);

    // normA overlaps attnB (s1); normB overlaps projO (s2)
    cudaStreamWaitEvent(s1, eaA, 0);
    norm_kernel<<<dim3(4096, 6, BATCH), 256, 0, s1>>>(attn, linv, 0);
    cudaEventRecord(enA, s1);
    cudaStreamWaitEvent(s2, eaB, 0);
    norm_kernel<<<dim3(4096, 6, BATCH), 256, 0, s2>>>(attn, linv, 6);
    cudaEventRecord(enB, s2);

    // s0: output projection
    cudaStreamWaitEvent(s0, ewo, 0);
    proj_kernel<<<pgrid, 256, 65536, s0>>>(ch, cl, wh[3], wl[3], w_b[3],
                                           out, nullptr, nullptr, 3);

    // join
    cudaStreamWaitEvent(s0, enA, 0);
    cudaStreamWaitEvent(s0, enB, 0);
}